// round 1
// baseline (speedup 1.0000x reference)
#include <cuda_runtime.h>

// Downsample1d: depthwise FIR [1/8,3/8,3/8,1/8], stride 2, reflect pad 1.
// x: [B=8, C=128, T=65536] fp32 -> out: [B, C, T/2] fp32.
// out[t] = k0*x[2t-1] + k1*x[2t] + k2*x[2t+1] + k3*x[2t+2]
// reflect: x[-1] -> x[1], x[T] -> x[T-2]
//
// Each thread: 4 outputs from one row, via two aligned float4 loads + 2 halo
// scalars, one float4 store. Fully coalesced; HBM-bound.

#define T_IN   65536
#define T_OUT  32768
#define QUADS_PER_ROW (T_OUT / 4)   // 8192
#define NROWS  (8 * 128)            // 1024

__global__ void __launch_bounds__(256) ds1d_kernel(
    const float* __restrict__ x,
    const float* __restrict__ kern,
    float* __restrict__ out)
{
    const long long gid = (long long)blockIdx.x * blockDim.x + threadIdx.x;
    const int q   = (int)(gid % QUADS_PER_ROW);        // quad within row
    const int row = (int)(gid / QUADS_PER_ROW);        // b*C + c
    if (row >= NROWS) return;

    const float k0 = __ldg(&kern[0]);
    const float k1 = __ldg(&kern[1]);
    const float k2 = __ldg(&kern[2]);
    const float k3 = __ldg(&kern[3]);

    const float* xrow = x + (long long)row * T_IN;
    const int i0 = q * 8;  // input base index

    const float4 a = __ldg((const float4*)(xrow + i0));
    const float4 b = __ldg((const float4*)(xrow + i0 + 4));

    // halo with reflect boundary
    const float xm1 = (i0 > 0)          ? __ldg(xrow + i0 - 1) : xrow[1];
    const float x8  = (i0 + 8 < T_IN)   ? __ldg(xrow + i0 + 8) : xrow[T_IN - 2];

    float4 o;
    o.x = k0 * xm1 + k1 * a.x + k2 * a.y + k3 * a.z;
    o.y = k0 * a.y + k1 * a.z + k2 * a.w + k3 * b.x;
    o.z = k0 * a.w + k1 * b.x + k2 * b.y + k3 * b.z;
    o.w = k0 * b.y + k1 * b.z + k2 * b.w + k3 * x8;

    *(float4*)(out + (long long)row * T_OUT + q * 4) = o;
}

extern "C" void kernel_launch(void* const* d_in, const int* in_sizes, int n_in,
                              void* d_out, int out_size)
{
    const float* x    = (const float*)d_in[0];
    const float* kern = (const float*)d_in[1];
    float* out        = (float*)d_out;

    const long long total_threads = (long long)NROWS * QUADS_PER_ROW; // 8,388,608
    const int block = 256;
    const int grid  = (int)((total_threads + block - 1) / block);     // 32768
    ds1d_kernel<<<grid, block>>>(x, kern, out);
}

// round 4
// speedup vs baseline: 1.0036x; 1.0036x over previous
#include <cuda_runtime.h>

// Downsample1d: depthwise FIR [1/8,3/8,3/8,1/8], stride 2, reflect pad 1.
// x: [B=8, C=128, T=65536] fp32 -> out: [B, C, T/2] fp32.
// out[t] = k0*x[2t-1] + k1*x[2t] + k2*x[2t+1] + k3*x[2t+2]
// reflect: x[-1] -> x[1], x[T] -> x[T-2]
//
// Each thread: 4 outputs from one row (two LDG.128 + one STG.128).
// Halo values come from neighbor lanes via warp shuffle (lane i-1 holds
// x[i0-1] in b.w, lane i+1 holds x[i0+8] in a.x); only the warp-edge lanes
// (0 and 31) do a scalar load. Streaming cache hints (ldcs/stcs) since data
// is touched exactly once.

#define T_IN   65536
#define T_OUT  32768
#define QUADS_PER_ROW (T_OUT / 4)   // 8192 quads per row
#define NROWS  (8 * 128)            // 1024

__global__ void __launch_bounds__(256) ds1d_kernel(
    const float* __restrict__ x,
    const float* __restrict__ kern,
    float* __restrict__ out)
{
    const int q    = blockIdx.x * blockDim.x + threadIdx.x;  // quad within row
    const int row  = blockIdx.y;                             // b*C + c
    const int lane = threadIdx.x & 31;

    const float k0 = __ldg(&kern[0]);
    const float k1 = __ldg(&kern[1]);
    const float k2 = __ldg(&kern[2]);
    const float k3 = __ldg(&kern[3]);

    const float* xrow = x + (long long)row * T_IN;
    const int i0 = q * 8;  // input base index

    const float4 a = __ldcs((const float4*)(xrow + i0));
    const float4 b = __ldcs((const float4*)(xrow + i0 + 4));

    // Halos via shuffle: lane-1's b.w == xrow[i0-1]; lane+1's a.x == xrow[i0+8]
    float xm1 = __shfl_up_sync(0xffffffffu, b.w, 1);
    if (lane == 0)
        xm1 = (i0 > 0) ? xrow[i0 - 1] : xrow[1];          // reflect left
    float x8 = __shfl_down_sync(0xffffffffu, a.x, 1);
    if (lane == 31)
        x8 = (i0 + 8 < T_IN) ? xrow[i0 + 8] : xrow[T_IN - 2];  // reflect right

    float4 o;
    o.x = k0 * xm1 + k1 * a.x + k2 * a.y + k3 * a.z;
    o.y = k0 * a.y + k1 * a.z + k2 * a.w + k3 * b.x;
    o.z = k0 * a.w + k1 * b.x + k2 * b.y + k3 * b.z;
    o.w = k0 * b.y + k1 * b.z + k2 * b.w + k3 * x8;

    __stcs((float4*)(out + (long long)row * T_OUT + q * 4), o);
}

extern "C" void kernel_launch(void* const* d_in, const int* in_sizes, int n_in,
                              void* d_out, int out_size)
{
    const float* x    = (const float*)d_in[0];
    const float* kern = (const float*)d_in[1];
    float* out        = (float*)d_out;

    dim3 block(256, 1, 1);
    dim3 grid(QUADS_PER_ROW / 256, NROWS, 1);  // (32, 1024)
    ds1d_kernel<<<grid, block>>>(x, kern, out);
}